// round 9
// baseline (speedup 1.0000x reference)
#include <cuda_runtime.h>
#include <cstdint>

// Problem constants (fixed by the reference: B=4, N=262144, G=128)
#define NBATCH 4
#define NPART  262144           // 2^18
#define TOTALP (NBATCH * NPART) // 1048576
#define GDIM   128
#define BOUNDC 3
#define TSZ    16               // tile edge in nodes
#define TPA    8                // tiles per axis
#define NKEY   (NBATCH * TPA * TPA * TPA)   // 2048
#define HALO   19               // 16 + 1 low + 2 high
#define HALO2  (HALO * HALO)                // 361
#define HALO3  (HALO * HALO * HALO)         // 6859
#define CAP    768              // bucket capacity (Poisson(512), 6+ sigma margin)
#define TILE_THREADS 512

__constant__ float kDT = 5e-4f;

// Scratch (static __device__ — allowed)
__device__ int    g_counts[NKEY];
__device__ float4 g_bucket[NKEY * CAP];   // {x,y,z, pid-as-bits}, 25 MB

// ---------------------------------------------------------------------------
__global__ void zero_kernel()
{
    const int t = blockIdx.x * blockDim.x + threadIdx.x;
    if (t < NKEY) g_counts[t] = 0;
}

// One-pass atomic append into per-tile buckets.
// cell c = floor(x*8) agrees with stencil base bx = floor(x*128 - 0.5):
// bx in [16c-1, 16c+15], stencil max node 16c+17 -> halo [16c-1, 16c+17].
__global__ void append_kernel(const float* __restrict__ x)
{
    const int pid = blockIdx.x * blockDim.x + threadIdx.x;
    if (pid >= TOTALP) return;
    const int b = pid >> 18;
    const float x0 = x[pid * 3 + 0];
    const float x1 = x[pid * 3 + 1];
    const float x2 = x[pid * 3 + 2];
    const int cx = min(max((int)(x0 * (float)TPA), 0), TPA - 1);
    const int cy = min(max((int)(x1 * (float)TPA), 0), TPA - 1);
    const int cz = min(max((int)(x2 * (float)TPA), 0), TPA - 1);
    const int key = (b << 9) | (cx << 6) | (cy << 3) | cz;
    const int pos = atomicAdd(&g_counts[key], 1);
    if (pos < CAP)
        g_bucket[key * CAP + pos] =
            make_float4(x0, x1, x2, __int_as_float(pid));
}

// ---------------------------------------------------------------------------
// One block per 16^3-node tile. Load the 19^3 halo once (grid_op applied per
// node), then each particle's 27 gathers come from shared memory.
// ---------------------------------------------------------------------------
__global__ __launch_bounds__(TILE_THREADS, 2)
void tile_kernel(const float* __restrict__ friction,
                 const float* __restrict__ pred,
                 const float* __restrict__ collider_floor,
                 const int*   __restrict__ statics,
                 float* __restrict__ out)
{
    extern __shared__ float4 s[];   // HALO3 float4 = 109744 B

    const int key = blockIdx.x;
    const int b  = key >> 9;
    const int cx = (key >> 6) & 7;
    const int cy = (key >> 3) & 7;
    const int cz = key & 7;
    const int tid = threadIdx.x;

    const float dx = 1.0f / (float)GDIM;
    const float mu  = friction[b];
    const float thr = collider_floor[b] + (float)BOUNDC * dx;

    const int t0x = TSZ * cx - 1;
    const int t0y = TSZ * cy - 1;
    const int t0z = TSZ * cz - 1;

    const float* __restrict__ gbase =
        pred + (size_t)b * (GDIM * GDIM * GDIM * 3);

    // ---- halo load + grid_op (once per node) ----
    for (int n = tid; n < HALO3; n += TILE_THREADS) {
        const int li = n / HALO2;
        const int rem = n - li * HALO2;
        const int lj = rem / HALO;
        const int lk = rem - lj * HALO;
        const int gi = min(max(t0x + li, 0), GDIM - 1);
        const int gj = min(max(t0y + lj, 0), GDIM - 1);
        const int gk = min(max(t0z + lk, 0), GDIM - 1);
        const size_t f = ((size_t)(gi * GDIM + gj) * GDIM + gk) * 3;
        float vx = gbase[f + 0];
        float vy = gbase[f + 1];
        float vz = gbase[f + 2];

        // floor Coulomb friction (normal = +y)
        if (((float)gj * dx) <= thr && vy < 0.0f) {
            const float rinv = rsqrtf(vx * vx + vz * vz + 1e-10f);
            const float sc = fmaxf(0.0f, fmaf(mu * vy, rinv, 1.0f));
            vx *= sc; vz *= sc; vy = 0.0f;
        }
        // boundary band clamps
        if ((gi < BOUNDC && vx < 0.0f) || (gi >= GDIM - BOUNDC && vx > 0.0f)) vx = 0.0f;
        if ((gj < BOUNDC && vy < 0.0f) || (gj >= GDIM - BOUNDC && vy > 0.0f)) vy = 0.0f;
        if ((gk < BOUNDC && vz < 0.0f) || (gk >= GDIM - BOUNDC && vz > 0.0f)) vz = 0.0f;

        s[n] = make_float4(vx, vy, vz, 0.0f);
    }
    __syncthreads();

    const int cnt = min(g_counts[key], CAP);
    const float4* __restrict__ bucket = g_bucket + (size_t)key * CAP;

    for (int idx = tid; idx < cnt; idx += TILE_THREADS) {
        const float4 p4 = bucket[idx];
        const int pid = __float_as_int(p4.w);
        const float x0 = p4.x, x1 = p4.y, x2 = p4.z;

        const float u0 = x0 * (float)GDIM;
        const float u1 = x1 * (float)GDIM;
        const float u2 = x2 * (float)GDIM;
        const int bx = (int)floorf(u0 - 0.5f);
        const int by = (int)floorf(u1 - 0.5f);
        const int bz = (int)floorf(u2 - 0.5f);
        const float f0 = u0 - (float)bx;
        const float f1 = u1 - (float)by;
        const float f2 = u2 - (float)bz;

        float w0[3], w1[3], w2[3];
        w0[0] = 0.5f * (1.5f - f0) * (1.5f - f0);
        w0[1] = 0.75f - (f0 - 1.0f) * (f0 - 1.0f);
        w0[2] = 0.5f * (f0 - 0.5f) * (f0 - 0.5f);
        w1[0] = 0.5f * (1.5f - f1) * (1.5f - f1);
        w1[1] = 0.75f - (f1 - 1.0f) * (f1 - 1.0f);
        w1[2] = 0.5f * (f1 - 0.5f) * (f1 - 0.5f);
        w2[0] = 0.5f * (1.5f - f2) * (1.5f - f2);
        w2[1] = 0.75f - (f2 - 1.0f) * (f2 - 1.0f);
        w2[2] = 0.5f * (f2 - 0.5f) * (f2 - 0.5f);

        // local (halo) indices of the clamped stencil nodes
        int rx[3], ry[3], rz[3];
        #pragma unroll
        for (int c = 0; c < 3; c++) {
            rx[c] = (min(max(bx + c, 0), GDIM - 1) - t0x) * HALO2;
            ry[c] = (min(max(by + c, 0), GDIM - 1) - t0y) * HALO;
            rz[c] =  min(max(bz + c, 0), GDIM - 1) - t0z;
        }

        float accx = 0.0f, accy = 0.0f, accz = 0.0f;
        #pragma unroll
        for (int i = 0; i < 3; i++) {
            #pragma unroll
            for (int j = 0; j < 3; j++) {
                const int rij = rx[i] + ry[j];
                const float wij = w0[i] * w1[j];
                #pragma unroll
                for (int k = 0; k < 3; k++) {
                    const float4 v = s[rij + rz[k]];
                    const float w = wij * w2[k];
                    accx = fmaf(w, v.x, accx);
                    accy = fmaf(w, v.y, accy);
                    accz = fmaf(w, v.z, accz);
                }
            }
        }

        const float m = (float)statics[pid];
        accx *= m; accy *= m; accz *= m;

        float* __restrict__ out_x = out;
        float* __restrict__ out_v = out + (size_t)TOTALP * 3;
        out_x[pid * 3 + 0] = fmaf(kDT, accx, x0);
        out_x[pid * 3 + 1] = fmaf(kDT, accy, x1);
        out_x[pid * 3 + 2] = fmaf(kDT, accz, x2);
        out_v[pid * 3 + 0] = accx;
        out_v[pid * 3 + 1] = accy;
        out_v[pid * 3 + 2] = accz;
    }
}

extern "C" void kernel_launch(void* const* d_in, const int* in_sizes, int n_in,
                              void* d_out, int out_size)
{
    // metadata order: x, v, friction, pred, collider_floor, statics_enabled, step
    const float* x              = (const float*)d_in[0];
    const float* friction       = (const float*)d_in[2];
    const float* pred           = (const float*)d_in[3];
    const float* collider_floor = (const float*)d_in[4];
    const int*   statics        = (const int*)d_in[5];

    float* out = (float*)d_out;

    const int smem_bytes = HALO3 * (int)sizeof(float4);   // 109744
    cudaFuncSetAttribute(tile_kernel,
                         cudaFuncAttributeMaxDynamicSharedMemorySize,
                         smem_bytes);

    zero_kernel<<<(NKEY + 255) / 256, 256>>>();
    append_kernel<<<TOTALP / 256, 256>>>(x);
    tile_kernel<<<NKEY, TILE_THREADS, smem_bytes>>>(
        friction, pred, collider_floor, statics, out);
}

// round 10
// speedup vs baseline: 2.0312x; 2.0312x over previous
#include <cuda_runtime.h>
#include <cstdint>

// Problem constants (fixed by the reference: B=4, N=262144, G=128)
#define NBATCH 4
#define NPART  262144          // 2^18
#define TOTALP (NBATCH * NPART)
#define GDIM   128
#define BOUNDC 3

__constant__ float kDT = 5e-4f;

struct PState {
    float w0[3], w1[3];
    float Wz[3];
    int   i0[3], i1[3];
    int   sq;
    bool  p0s, p1s;
    bool  zlow[3], zhigh[3];
    float x0, x1, x2;
    const float4* g4;
    float accx, accy, accz;
};

__device__ __forceinline__ void setup_particle(PState& P,
                                               const float* __restrict__ x,
                                               const float* __restrict__ pred,
                                               int pid)
{
    const int b = pid >> 18;
    const float inv_dx = (float)GDIM;

    P.x0 = x[pid * 3 + 0];
    P.x1 = x[pid * 3 + 1];
    P.x2 = x[pid * 3 + 2];

    const float p0f = P.x0 * inv_dx;
    const float p1f = P.x1 * inv_dx;
    const float p2f = P.x2 * inv_dx;
    const int bx = (int)floorf(p0f - 0.5f);
    const int by = (int)floorf(p1f - 0.5f);
    const int bz = (int)floorf(p2f - 0.5f);
    const float f0 = p0f - (float)bx;
    const float f1 = p1f - (float)by;
    const float f2 = p2f - (float)bz;

    P.w0[0] = 0.5f * (1.5f - f0) * (1.5f - f0);
    P.w0[1] = 0.75f - (f0 - 1.0f) * (f0 - 1.0f);
    P.w0[2] = 0.5f * (f0 - 0.5f) * (f0 - 0.5f);
    P.w1[0] = 0.5f * (1.5f - f1) * (1.5f - f1);
    P.w1[1] = 0.75f - (f1 - 1.0f) * (f1 - 1.0f);
    P.w1[2] = 0.5f * (f1 - 0.5f) * (f1 - 0.5f);
    float w2[3];
    w2[0] = 0.5f * (1.5f - f2) * (1.5f - f2);
    w2[1] = 0.75f - (f2 - 1.0f) * (f2 - 1.0f);
    w2[2] = 0.5f * (f2 - 0.5f) * (f2 - 0.5f);

    #pragma unroll
    for (int c = 0; c < 3; c++) {
        P.i0[c] = min(max(bx + c, 0), GDIM - 1);
        P.i1[c] = min(max(by + c, 0), GDIM - 1);
    }

    const int s = min(max(bz, 0), GDIM - 3);
    P.Wz[0] = 0.0f; P.Wz[1] = 0.0f; P.Wz[2] = 0.0f;
    #pragma unroll
    for (int k = 0; k < 3; k++) {
        const int idx = min(max(bz + k, 0), GDIM - 1) - s;
        #pragma unroll
        for (int t = 0; t < 3; t++)
            P.Wz[t] += (idx == t) ? w2[k] : 0.0f;
    }

    const int s3 = 3 * s;
    const int r  = s3 & 3;
    P.p0s = (r & 1) != 0;
    P.p1s = (r & 2) != 0;
    P.sq = s3 >> 2;

    #pragma unroll
    for (int t = 0; t < 3; t++) {
        const int gk = s + t;
        P.zlow[t]  = gk < BOUNDC;
        P.zhigh[t] = gk >= GDIM - BOUNDC;
    }

    P.g4 = (const float4*)(pred) + (size_t)b * (GDIM * GDIM * GDIM * 3 / 4);
    P.accx = 0.0f; P.accy = 0.0f; P.accz = 0.0f;
}

// Process one (i,j) z-row of a particle from a preloaded 48B window.
__device__ __forceinline__ void row_accum(PState& P, int i, int j,
                                          float4 q0, float4 q1, float4 q2,
                                          float mu, float thr)
{
    const float dx = 1.0f / (float)GDIM;
    const int gi = P.i0[i];
    const int gj = P.i1[j];
    const float wij = P.w0[i] * P.w1[j];
    const bool nearf = ((float)gj * dx) <= thr;
    const bool xlow  = gi < BOUNDC;
    const bool xhigh = gi >= GDIM - BOUNDC;
    const bool ylow  = gj < BOUNDC;
    const bool yhigh = gj >= GDIM - BOUNDC;

    const float wq[12] = {q0.x, q0.y, q0.z, q0.w,
                          q1.x, q1.y, q1.z, q1.w,
                          q2.x, q2.y, q2.z, q2.w};
    float v[9];
    #pragma unroll
    for (int t = 0; t < 9; t++) {
        const float a  = P.p0s ? wq[t + 1] : wq[t];
        const float bb = P.p0s ? wq[t + 3] : wq[t + 2];
        v[t] = P.p1s ? bb : a;
    }

    #pragma unroll
    for (int t = 0; t < 3; t++) {
        float vx_ = v[3 * t + 0];
        float vy_ = v[3 * t + 1];
        float vz_ = v[3 * t + 2];

        if (nearf && vy_ < 0.0f) {
            const float rinv = rsqrtf(vx_ * vx_ + vz_ * vz_ + 1e-10f);
            const float sc = fmaxf(0.0f, fmaf(mu * vy_, rinv, 1.0f));
            vx_ *= sc; vz_ *= sc; vy_ = 0.0f;
        }
        if ((xlow && vx_ < 0.0f) || (xhigh && vx_ > 0.0f)) vx_ = 0.0f;
        if ((ylow && vy_ < 0.0f) || (yhigh && vy_ > 0.0f)) vy_ = 0.0f;
        if ((P.zlow[t] && vz_ < 0.0f) || (P.zhigh[t] && vz_ > 0.0f)) vz_ = 0.0f;

        const float w = wij * P.Wz[t];
        P.accx = fmaf(w, vx_, P.accx);
        P.accy = fmaf(w, vy_, P.accy);
        P.accz = fmaf(w, vz_, P.accz);
    }
}

__device__ __forceinline__ void finish_particle(PState& P,
                                                const int* __restrict__ statics,
                                                float* __restrict__ out, int pid)
{
    const float m = (float)statics[pid];
    const float ax = P.accx * m, ay = P.accy * m, az = P.accz * m;
    float* __restrict__ out_x = out;
    float* __restrict__ out_v = out + (size_t)TOTALP * 3;
    out_x[pid * 3 + 0] = fmaf(kDT, ax, P.x0);
    out_x[pid * 3 + 1] = fmaf(kDT, ay, P.x1);
    out_x[pid * 3 + 2] = fmaf(kDT, az, P.x2);
    out_v[pid * 3 + 0] = ax;
    out_v[pid * 3 + 1] = ay;
    out_v[pid * 3 + 2] = az;
}

// Two particles per thread, gather streams interleaved row-by-row for 2x MLP.
__global__ __launch_bounds__(256, 3)
void fused2_kernel(const float* __restrict__ x,
                   const float* __restrict__ friction,
                   const float* __restrict__ pred,
                   const float* __restrict__ collider_floor,
                   const int*   __restrict__ statics,
                   float* __restrict__ out)
{
    const int tid = threadIdx.x;
    const int pidA = blockIdx.x * 512 + tid;
    const int pidB = pidA + 256;

    const float dx = 1.0f / (float)GDIM;

    PState A, B;
    setup_particle(A, x, pred, pidA);
    setup_particle(B, x, pred, pidB);

    const int bA = pidA >> 18;
    const int bB = pidB >> 18;
    const float muA  = friction[bA];
    const float thrA = collider_floor[bA] + (float)BOUNDC * dx;
    const float muB  = friction[bB];
    const float thrB = collider_floor[bB] + (float)BOUNDC * dx;

    #pragma unroll
    for (int i = 0; i < 3; i++) {
        #pragma unroll
        for (int j = 0; j < 3; j++) {
            const int fA = (A.i0[i] * GDIM + A.i1[j]) * 96 + A.sq;
            const int fB = (B.i0[i] * GDIM + B.i1[j]) * 96 + B.sq;
            // issue all six loads before consuming either row
            const float4 a0 = __ldg(A.g4 + fA + 0);
            const float4 a1 = __ldg(A.g4 + fA + 1);
            const float4 a2 = __ldg(A.g4 + fA + 2);
            const float4 b0 = __ldg(B.g4 + fB + 0);
            const float4 b1 = __ldg(B.g4 + fB + 1);
            const float4 b2 = __ldg(B.g4 + fB + 2);
            row_accum(A, i, j, a0, a1, a2, muA, thrA);
            row_accum(B, i, j, b0, b1, b2, muB, thrB);
        }
    }

    finish_particle(A, statics, out, pidA);
    finish_particle(B, statics, out, pidB);
}

extern "C" void kernel_launch(void* const* d_in, const int* in_sizes, int n_in,
                              void* d_out, int out_size)
{
    // metadata order: x, v, friction, pred, collider_floor, statics_enabled, step
    const float* x              = (const float*)d_in[0];
    const float* friction       = (const float*)d_in[2];
    const float* pred           = (const float*)d_in[3];
    const float* collider_floor = (const float*)d_in[4];
    const int*   statics        = (const int*)d_in[5];

    float* out = (float*)d_out;

    fused2_kernel<<<TOTALP / 512, 256>>>(x, friction, pred, collider_floor,
                                         statics, out);
}

// round 11
// speedup vs baseline: 2.3199x; 1.1421x over previous
#include <cuda_runtime.h>
#include <cstdint>

// Problem constants (fixed by the reference: B=4, N=262144, G=128)
#define NBATCH 4
#define NPART  262144          // 2^18
#define TOTALP (NBATCH * NPART)
#define GDIM   128
#define BOUNDC 3

__constant__ float kDT = 5e-4f;

// Fused grid_op + g2p (R3 structure), occupancy-tuned to 5 blocks/SM.
// Each z-row of 3 nodes (9 floats, 36B) is fetched with 3 aligned LDG.128
// covering a 48B window; r = (3s)&3 is uniform per particle so extraction is
// a 2-predicate SEL tree.
__global__ __launch_bounds__(256, 5)
void fused_kernel(const float* __restrict__ x,
                  const float* __restrict__ friction,
                  const float* __restrict__ pred,
                  const float* __restrict__ collider_floor,
                  const int*   __restrict__ statics,
                  float* __restrict__ out)
{
    const int pid = blockIdx.x * blockDim.x + threadIdx.x;
    if (pid >= TOTALP) return;

    const int b = pid >> 18;
    const float dx = 1.0f / (float)GDIM;
    const float inv_dx = (float)GDIM;

    const float x0 = x[pid * 3 + 0];
    const float x1 = x[pid * 3 + 1];
    const float x2 = x[pid * 3 + 2];

    const float mu  = friction[b];
    const float thr = collider_floor[b] + (float)BOUNDC * dx;

    // ---- stencil setup ----
    float w0[3], w1[3], w2[3];
    int   i0[3], i1[3];
    int   s;
    float Wz[3];
    {
        const float p0f = x0 * inv_dx;
        const float p1f = x1 * inv_dx;
        const float p2f = x2 * inv_dx;
        const int bx = (int)floorf(p0f - 0.5f);
        const int by = (int)floorf(p1f - 0.5f);
        const int bz = (int)floorf(p2f - 0.5f);
        const float f0 = p0f - (float)bx;
        const float f1 = p1f - (float)by;
        const float f2 = p2f - (float)bz;

        w0[0] = 0.5f * (1.5f - f0) * (1.5f - f0);
        w0[1] = 0.75f - (f0 - 1.0f) * (f0 - 1.0f);
        w0[2] = 0.5f * (f0 - 0.5f) * (f0 - 0.5f);
        w1[0] = 0.5f * (1.5f - f1) * (1.5f - f1);
        w1[1] = 0.75f - (f1 - 1.0f) * (f1 - 1.0f);
        w1[2] = 0.5f * (f1 - 0.5f) * (f1 - 0.5f);
        w2[0] = 0.5f * (1.5f - f2) * (1.5f - f2);
        w2[1] = 0.75f - (f2 - 1.0f) * (f2 - 1.0f);
        w2[2] = 0.5f * (f2 - 0.5f) * (f2 - 0.5f);

        #pragma unroll
        for (int c = 0; c < 3; c++) {
            i0[c] = min(max(bx + c, 0), GDIM - 1);
            i1[c] = min(max(by + c, 0), GDIM - 1);
        }

        s = min(max(bz, 0), GDIM - 3);
        Wz[0] = 0.0f; Wz[1] = 0.0f; Wz[2] = 0.0f;
        #pragma unroll
        for (int k = 0; k < 3; k++) {
            const int idx = min(max(bz + k, 0), GDIM - 1) - s;
            #pragma unroll
            for (int t = 0; t < 3; t++)
                Wz[t] += (idx == t) ? w2[k] : 0.0f;
        }
    }

    const int s3 = 3 * s;
    const int r  = s3 & 3;             // uniform per particle
    const bool p0s = (r & 1) != 0;
    const bool p1s = (r & 2) != 0;
    const int sq = s3 >> 2;

    // hoisted per-axis clamp/contact booleans
    bool zlow[3], zhigh[3], xlo[3], xhi[3], ylo[3], yhi[3], nearf[3];
    #pragma unroll
    for (int t = 0; t < 3; t++) {
        const int gk = s + t;
        zlow[t]  = gk < BOUNDC;
        zhigh[t] = gk >= GDIM - BOUNDC;
        xlo[t] = i0[t] < BOUNDC;
        xhi[t] = i0[t] >= GDIM - BOUNDC;
        ylo[t] = i1[t] < BOUNDC;
        yhi[t] = i1[t] >= GDIM - BOUNDC;
        nearf[t] = ((float)i1[t] * dx) <= thr;
    }

    const float4* __restrict__ g4 =
        (const float4*)(pred) + (size_t)b * (GDIM * GDIM * GDIM * 3 / 4);

    float accx = 0.0f, accy = 0.0f, accz = 0.0f;

    #pragma unroll
    for (int i = 0; i < 3; i++) {
        const int ibase = i0[i] * GDIM * 96 + sq;
        #pragma unroll
        for (int j = 0; j < 3; j++) {
            const float wij = w0[i] * w1[j];

            const int f4 = ibase + i1[j] * 96;
            const float4 q0 = __ldg(g4 + f4 + 0);
            const float4 q1 = __ldg(g4 + f4 + 1);
            const float4 q2 = __ldg(g4 + f4 + 2);

            const float wq[12] = {q0.x, q0.y, q0.z, q0.w,
                                  q1.x, q1.y, q1.z, q1.w,
                                  q2.x, q2.y, q2.z, q2.w};
            float v[9];
            #pragma unroll
            for (int t = 0; t < 9; t++) {
                const float a  = p0s ? wq[t + 1] : wq[t];
                const float bb = p0s ? wq[t + 3] : wq[t + 2];
                v[t] = p1s ? bb : a;
            }

            #pragma unroll
            for (int t = 0; t < 3; t++) {
                float vx_ = v[3 * t + 0];
                float vy_ = v[3 * t + 1];
                float vz_ = v[3 * t + 2];

                // floor Coulomb friction (normal = +y)
                if (nearf[j] && vy_ < 0.0f) {
                    const float rinv = rsqrtf(vx_ * vx_ + vz_ * vz_ + 1e-10f);
                    const float sc = fmaxf(0.0f, fmaf(mu * vy_, rinv, 1.0f));
                    vx_ *= sc; vz_ *= sc; vy_ = 0.0f;
                }
                // boundary band clamps
                if ((xlo[i] && vx_ < 0.0f) || (xhi[i] && vx_ > 0.0f)) vx_ = 0.0f;
                if ((ylo[j] && vy_ < 0.0f) || (yhi[j] && vy_ > 0.0f)) vy_ = 0.0f;
                if ((zlow[t] && vz_ < 0.0f) || (zhigh[t] && vz_ > 0.0f)) vz_ = 0.0f;

                const float w = wij * Wz[t];
                accx = fmaf(w, vx_, accx);
                accy = fmaf(w, vy_, accy);
                accz = fmaf(w, vz_, accz);
            }
        }
    }

    const float m = (float)statics[pid];
    accx *= m; accy *= m; accz *= m;

    float* __restrict__ out_x = out;
    float* __restrict__ out_v = out + (size_t)TOTALP * 3;

    out_x[pid * 3 + 0] = fmaf(kDT, accx, x0);
    out_x[pid * 3 + 1] = fmaf(kDT, accy, x1);
    out_x[pid * 3 + 2] = fmaf(kDT, accz, x2);
    out_v[pid * 3 + 0] = accx;
    out_v[pid * 3 + 1] = accy;
    out_v[pid * 3 + 2] = accz;
}

extern "C" void kernel_launch(void* const* d_in, const int* in_sizes, int n_in,
                              void* d_out, int out_size)
{
    // metadata order: x, v, friction, pred, collider_floor, statics_enabled, step
    const float* x              = (const float*)d_in[0];
    const float* friction       = (const float*)d_in[2];
    const float* pred           = (const float*)d_in[3];
    const float* collider_floor = (const float*)d_in[4];
    const int*   statics        = (const int*)d_in[5];

    float* out = (float*)d_out;

    const int threads = 256;
    fused_kernel<<<(TOTALP + threads - 1) / threads, threads>>>(
        x, friction, pred, collider_floor, statics, out);
}